// round 13
// baseline (speedup 1.0000x reference)
#include <cuda_runtime.h>
#include <cuda_fp16.h>
#include <cstdint>

// Problem sizes
#define NROW 2048   // B*DEPTH = 16*128
#define NK   1024   // HID
#define NC   2048   // DIN == DOUT
#define B_   16

// ---------------------------------------------------------------------------
// fp16 hi/lo split scratch (device globals, 16B-aligned for cp.async/vector IO)
// ---------------------------------------------------------------------------
__device__ __align__(256) __half g_Lhi[NROW * NK], g_Llo[NROW * NK];      // logits split
__device__ __align__(256) __half g_Wthi[2][NC * NK], g_Wtlo[2][NC * NK];  // W^T split
__device__ __align__(256) __half g_Vhi[2][NROW * NC], g_Vlo[2][NROW * NC];// iv(0)/ov(1)

// ---------------------------------------------------------------------------
// helpers (all plain sm_80-era PTX — valid at target compute_103)
// ---------------------------------------------------------------------------
__device__ __forceinline__ uint32_t smem_to_u32(const void* p) {
    uint32_t a;
    asm("{ .reg .u64 t; cvta.to.shared.u64 t, %1; cvt.u32.u64 %0, t; }" : "=r"(a) : "l"(p));
    return a;
}

#define CPA16(s, g) \
    asm volatile("cp.async.cg.shared.global [%0], [%1], 16;" :: "r"(s), "l"(g))
#define CPCOMMIT() asm volatile("cp.async.commit_group;")
#define CPWAIT(n)  asm volatile("cp.async.wait_group %0;" :: "n"(n))

#define LDSM4(r0, r1, r2, r3, a) \
    asm volatile("ldmatrix.sync.aligned.m8n8.x4.shared.b16 {%0,%1,%2,%3}, [%4];" \
                 : "=r"(r0), "=r"(r1), "=r"(r2), "=r"(r3) : "r"(a))
#define LDSM4T(r0, r1, r2, r3, a) \
    asm volatile("ldmatrix.sync.aligned.m8n8.x4.trans.shared.b16 {%0,%1,%2,%3}, [%4];" \
                 : "=r"(r0), "=r"(r1), "=r"(r2), "=r"(r3) : "r"(a))

#define MMA(c, a, b) \
    asm volatile("mma.sync.aligned.m16n8k16.row.col.f32.f16.f16.f32 " \
                 "{%0,%1,%2,%3},{%4,%5,%6,%7},{%8,%9},{%0,%1,%2,%3};" \
                 : "+f"((c)[0]), "+f"((c)[1]), "+f"((c)[2]), "+f"((c)[3]) \
                 : "r"((a)[0]), "r"((a)[1]), "r"((a)[2]), "r"((a)[3]), \
                   "r"((b)[0]), "r"((b)[1]))

__device__ __forceinline__ float clamp5(float v) {
    return fminf(fmaxf(v, -5.0f), 5.0f);
}

// ---------------------------------------------------------------------------
// Prep 1: split logits fp32 -> fp16 hi/lo (same [row][k] layout)
// ---------------------------------------------------------------------------
__global__ void k_split(const float* __restrict__ X) {
    int i = blockIdx.x * blockDim.x + threadIdx.x;   // one float4 each
    if (i >= NROW * NK / 4) return;
    float4 v = reinterpret_cast<const float4*>(X)[i];
    __half h0 = __float2half_rn(v.x), h1 = __float2half_rn(v.y);
    __half h2 = __float2half_rn(v.z), h3 = __float2half_rn(v.w);
    __half2* H = reinterpret_cast<__half2*>(g_Lhi);
    __half2* L = reinterpret_cast<__half2*>(g_Llo);
    H[2 * i]     = __halves2half2(h0, h1);
    H[2 * i + 1] = __halves2half2(h2, h3);
    L[2 * i]     = __halves2half2(__float2half_rn(v.x - __half2float(h0)),
                                  __float2half_rn(v.y - __half2float(h1)));
    L[2 * i + 1] = __halves2half2(__float2half_rn(v.z - __half2float(h2)),
                                  __float2half_rn(v.w - __half2float(h3)));
}

// ---------------------------------------------------------------------------
// Prep 2: transpose + split W [1024 hid][2048 col] -> Wt[which] [col][hid]
// ---------------------------------------------------------------------------
__global__ void k_wtrans(const float* __restrict__ W, int which) {
    __shared__ float t[32][33];
    const int c0 = blockIdx.x * 32, h0 = blockIdx.y * 32;
    const int tx = threadIdx.x, ty = threadIdx.y;    // 32 x 8
#pragma unroll
    for (int j = 0; j < 4; j++)
        t[ty + j * 8][tx] = W[(size_t)(h0 + ty + j * 8) * NC + c0 + tx];
    __syncthreads();
    __half* hi = g_Wthi[which];
    __half* lo = g_Wtlo[which];
#pragma unroll
    for (int j = 0; j < 4; j++) {
        float v = t[tx][ty + j * 8];
        __half h = __float2half_rn(v);
        size_t off = (size_t)(c0 + ty + j * 8) * NK + h0 + tx;
        hi[off] = h;
        lo[off] = __float2half_rn(v - __half2float(h));
    }
}

// ===========================================================================
// Phase 1: V[z] = clamp(L @ Wt[z]^T + bias[z]).  M=2048, N=2048, K=1024.
// CTA 128x256, BK=32, 8 warps as 2m x 4n, WARP TILE 64x64 (M_t=4, N_t=8):
// MMA per LDSM.x4 = 6 (was 4) -> smem crossbar no longer the binder.
// 1 CTA/SM (255-reg budget), 2-stage cp.async ring.
// SMEM stage: Ah|Al [128][40] + Bh|Bl [256][40] halves = 61440B.
// ===========================================================================
#define P1_APLANE 10240
#define P1_BPLANE 20480
#define P1_STAGE  61440

__global__ __launch_bounds__(256, 1)
void k_gen(const float* __restrict__ bi, const float* __restrict__ bo)
{
    extern __shared__ char smem[];
    const uint32_t sbase = smem_to_u32(smem);
    const int tid = threadIdx.x, lane = tid & 31, wid = tid >> 5;
    const int wm = wid >> 2, wn = wid & 3;       // 2m x 4n, warp tile 64x64
    const int row0 = blockIdx.y * 128, col0 = blockIdx.x * 256;
    const int z = blockIdx.z;

    const __half* __restrict__ pAh = g_Lhi + (size_t)row0 * NK;
    const __half* __restrict__ pAl = g_Llo + (size_t)row0 * NK;
    const __half* __restrict__ pBh = g_Wthi[z] + (size_t)col0 * NK;
    const __half* __restrict__ pBl = g_Wtlo[z] + (size_t)col0 * NK;

    float acc[4][8][4];
#pragma unroll
    for (int mi = 0; mi < 4; mi++)
#pragma unroll
        for (int ni = 0; ni < 8; ni++)
#pragma unroll
            for (int q = 0; q < 4; q++) acc[mi][ni][q] = 0.0f;

#define GEN_LOAD(s_, st_) do {                                                  \
    const int k0_ = (s_) * 32;                                                  \
    const uint32_t d0_ = sbase + (uint32_t)(st_) * P1_STAGE;                    \
    _Pragma("unroll")                                                           \
    for (int i_ = 0; i_ < 4; i_++) {            /* A: 1024 chunks */            \
        const int idx_ = tid + i_ * 256;                                        \
        const int p_ = idx_ >> 9, r_ = (idx_ >> 2) & 127, kc_ = idx_ & 3;       \
        CPA16(d0_ + p_ * P1_APLANE + r_ * 80 + kc_ * 16,                        \
              (p_ ? pAl : pAh) + (size_t)r_ * NK + k0_ + kc_ * 8);              \
    }                                                                           \
    _Pragma("unroll")                                                           \
    for (int i_ = 0; i_ < 8; i_++) {            /* B: 2048 chunks */            \
        const int idx_ = tid + i_ * 256;                                        \
        const int p_ = idx_ >> 10, r_ = (idx_ >> 2) & 255, kc_ = idx_ & 3;      \
        CPA16(d0_ + 2 * P1_APLANE + p_ * P1_BPLANE + r_ * 80 + kc_ * 16,        \
              (p_ ? pBl : pBh) + (size_t)r_ * NK + k0_ + kc_ * 8);              \
    }                                                                           \
    CPCOMMIT();                                                                 \
} while (0)

#define GEN_COMP(st_) do {                                                      \
    const uint32_t sb_ = sbase + (uint32_t)(st_) * P1_STAGE;                    \
    _Pragma("unroll")                                                           \
    for (int ks = 0; ks < 2; ks++) {                                            \
        uint32_t ah[4][4], al[4][4];                                            \
        _Pragma("unroll")                                                       \
        for (int mi = 0; mi < 4; mi++) {                                        \
            uint32_t ra = sb_ + ((wm * 64 + mi * 16 + (lane & 15)) * 40         \
                                 + ks * 16 + ((lane >> 4) << 3)) * 2;           \
            LDSM4(ah[mi][0], ah[mi][1], ah[mi][2], ah[mi][3], ra);              \
            LDSM4(al[mi][0], al[mi][1], al[mi][2], al[mi][3], ra + P1_APLANE);  \
        }                                                                       \
        _Pragma("unroll")                                                       \
        for (int ng = 0; ng < 4; ng++) {                                        \
            uint32_t bh[2][2], bl[2][2];                                        \
            uint32_t rb = sb_ + 2 * P1_APLANE                                   \
                + ((wn * 64 + ng * 16 + ((lane >> 4) << 3) + (lane & 7)) * 40   \
                   + ks * 16 + (((lane >> 3) & 1) << 3)) * 2;                   \
            LDSM4(bh[0][0], bh[0][1], bh[1][0], bh[1][1], rb);                  \
            LDSM4(bl[0][0], bl[0][1], bl[1][0], bl[1][1], rb + P1_BPLANE);      \
            _Pragma("unroll")                                                   \
            for (int mi = 0; mi < 4; mi++)                                      \
                _Pragma("unroll")                                               \
                for (int nn = 0; nn < 2; nn++) {                                \
                    MMA(acc[mi][2 * ng + nn], ah[mi], bh[nn]);                  \
                    MMA(acc[mi][2 * ng + nn], ah[mi], bl[nn]);                  \
                    MMA(acc[mi][2 * ng + nn], al[mi], bh[nn]);                  \
                }                                                               \
        }                                                                       \
    }                                                                           \
} while (0)

    GEN_LOAD(0, 0);
    for (int s = 0; s < 32; s++) {
        if (s + 1 < 32) { GEN_LOAD(s + 1, (s + 1) & 1); CPWAIT(1); }
        else            { CPWAIT(0); }
        __syncthreads();
        GEN_COMP(s & 1);
        __syncthreads();
    }

    // epilogue: +bias, clamp, fp16 split, natural [row][col] store
    const float* __restrict__ bias = z ? bo : bi;
    __half* __restrict__ Oh = g_Vhi[z];
    __half* __restrict__ Ol = g_Vlo[z];
#pragma unroll
    for (int mi = 0; mi < 4; mi++)
#pragma unroll
        for (int ni = 0; ni < 8; ni++) {
            int rr = row0 + wm * 64 + mi * 16 + (lane >> 2);
            int gc = col0 + wn * 64 + ni * 8 + (lane & 3) * 2;
            float b0v = __ldg(bias + gc), b1v = __ldg(bias + gc + 1);

            float v0 = clamp5(acc[mi][ni][0] + b0v);
            float v1 = clamp5(acc[mi][ni][1] + b1v);
            __half h0 = __float2half_rn(v0), h1 = __float2half_rn(v1);
            *(__half2*)(Oh + (size_t)rr * NC + gc) = __halves2half2(h0, h1);
            *(__half2*)(Ol + (size_t)rr * NC + gc) =
                __halves2half2(__float2half_rn(v0 - __half2float(h0)),
                               __float2half_rn(v1 - __half2float(h1)));

            float v2 = clamp5(acc[mi][ni][2] + b0v);
            float v3 = clamp5(acc[mi][ni][3] + b1v);
            __half h2 = __float2half_rn(v2), h3 = __float2half_rn(v3);
            *(__half2*)(Oh + (size_t)(rr + 8) * NC + gc) = __halves2half2(h2, h3);
            *(__half2*)(Ol + (size_t)(rr + 8) * NC + gc) =
                __halves2half2(__float2half_rn(v2 - __half2float(h2)),
                               __float2half_rn(v3 - __half2float(h3)));
        }
#undef GEN_LOAD
#undef GEN_COMP
}

// ===========================================================================
// Phase 2: out[b] = wp[b] + iv[b]^T @ ov[b].  Per batch M=N=2048, K=128.
// CTA 128x256, warp tile 64x64, 2-stage ring. iv/ov stored [d][col] ->
// fragments via ldmatrix.trans. wp read from global in the epilogue.
// SMEM stage: Ah|Al [32][136] + Bh|Bl [32][264] halves = 51200B.
// ===========================================================================
#define P2_APLANE 8704
#define P2_BPLANE 16896
#define P2_STAGE  51200

__global__ __launch_bounds__(256, 1)
void k_outer(const float* __restrict__ wp, float* __restrict__ out)
{
    extern __shared__ char smem[];
    const uint32_t sbase = smem_to_u32(smem);
    const int tid = threadIdx.x, lane = tid & 31, wid = tid >> 5;
    const int wm = wid >> 2, wn = wid & 3;       // 2m x 4n, warp tile 64x64
    const int b = blockIdx.z;
    const int i0 = blockIdx.y * 128, j0 = blockIdx.x * 256;

    const __half* __restrict__ pAh = g_Vhi[0] + (size_t)(b * 128) * NC + i0;
    const __half* __restrict__ pAl = g_Vlo[0] + (size_t)(b * 128) * NC + i0;
    const __half* __restrict__ pBh = g_Vhi[1] + (size_t)(b * 128) * NC + j0;
    const __half* __restrict__ pBl = g_Vlo[1] + (size_t)(b * 128) * NC + j0;

    float acc[4][8][4];
#pragma unroll
    for (int mi = 0; mi < 4; mi++)
#pragma unroll
        for (int ni = 0; ni < 8; ni++)
#pragma unroll
            for (int q = 0; q < 4; q++) acc[mi][ni][q] = 0.0f;

#define OUT_LOAD(s_, st_) do {                                                  \
    const int d0_ = (s_) * 32;                                                  \
    const uint32_t b0_ = sbase + (uint32_t)(st_) * P2_STAGE;                    \
    _Pragma("unroll")                                                           \
    for (int i_ = 0; i_ < 4; i_++) {            /* A: 1024 chunks */            \
        const int idx_ = tid + i_ * 256;                                        \
        const int p_ = idx_ >> 9, r_ = (idx_ >> 4) & 31, ch_ = idx_ & 15;       \
        CPA16(b0_ + p_ * P2_APLANE + r_ * 272 + ch_ * 16,                       \
              (p_ ? pAl : pAh) + (size_t)(d0_ + r_) * NC + ch_ * 8);            \
    }                                                                           \
    _Pragma("unroll")                                                           \
    for (int i_ = 0; i_ < 8; i_++) {            /* B: 2048 chunks */            \
        const int idx_ = tid + i_ * 256;                                        \
        const int p_ = idx_ >> 10, r_ = (idx_ >> 5) & 31, ch_ = idx_ & 31;      \
        CPA16(b0_ + 2 * P2_APLANE + p_ * P2_BPLANE + r_ * 528 + ch_ * 16,       \
              (p_ ? pBl : pBh) + (size_t)(d0_ + r_) * NC + ch_ * 8);            \
    }                                                                           \
    CPCOMMIT();                                                                 \
} while (0)

#define OUT_COMP(st_) do {                                                      \
    const uint32_t sb_ = sbase + (uint32_t)(st_) * P2_STAGE;                    \
    _Pragma("unroll")                                                           \
    for (int ks = 0; ks < 2; ks++) {                                            \
        uint32_t ah[4][4], al[4][4];                                            \
        _Pragma("unroll")                                                       \
        for (int mi = 0; mi < 4; mi++) {                                        \
            uint32_t ra = sb_                                                   \
                + ((ks * 16 + ((lane >> 4) << 3) + (lane & 7)) * 136            \
                   + wm * 64 + mi * 16 + (((lane >> 3) & 1) << 3)) * 2;         \
            LDSM4T(ah[mi][0], ah[mi][1], ah[mi][2], ah[mi][3], ra);             \
            LDSM4T(al[mi][0], al[mi][1], al[mi][2], al[mi][3], ra + P2_APLANE); \
        }                                                                       \
        _Pragma("unroll")                                                       \
        for (int ng = 0; ng < 4; ng++) {                                        \
            uint32_t bh[2][2], bl[2][2];                                        \
            uint32_t rb = sb_ + 2 * P2_APLANE                                   \
                + ((ks * 16 + (((lane >> 3) & 1) << 3) + (lane & 7)) * 264      \
                   + wn * 64 + ng * 16 + ((lane >> 4) << 3)) * 2;               \
            LDSM4T(bh[0][0], bh[0][1], bh[1][0], bh[1][1], rb);                 \
            LDSM4T(bl[0][0], bl[0][1], bl[1][0], bl[1][1], rb + P2_BPLANE);     \
            _Pragma("unroll")                                                   \
            for (int mi = 0; mi < 4; mi++)                                      \
                _Pragma("unroll")                                               \
                for (int nn = 0; nn < 2; nn++) {                                \
                    MMA(acc[mi][2 * ng + nn], ah[mi], bh[nn]);                  \
                    MMA(acc[mi][2 * ng + nn], ah[mi], bl[nn]);                  \
                    MMA(acc[mi][2 * ng + nn], al[mi], bh[nn]);                  \
                }                                                               \
        }                                                                       \
    }                                                                           \
} while (0)

    OUT_LOAD(0, 0);
    for (int s = 0; s < 4; s++) {
        if (s + 1 < 4) { OUT_LOAD(s + 1, (s + 1) & 1); CPWAIT(1); }
        else           { CPWAIT(0); }
        __syncthreads();
        OUT_COMP(s & 1);
        __syncthreads();
    }

    // epilogue: + weight_params (global), fp32 store
#pragma unroll
    for (int mi = 0; mi < 4; mi++)
#pragma unroll
        for (int ni = 0; ni < 8; ni++) {
            int rr = i0 + wm * 64 + mi * 16 + (lane >> 2);
            int cc = j0 + wn * 64 + ni * 8 + (lane & 3) * 2;
            size_t g0 = ((size_t)b * NC + rr) * NC + cc;
            size_t g1 = g0 + (size_t)8 * NC;
            float2 w0 = *(const float2*)(wp + g0);
            float2 w1 = *(const float2*)(wp + g1);
            *(float2*)(out + g0) =
                make_float2(acc[mi][ni][0] + w0.x, acc[mi][ni][1] + w0.y);
            *(float2*)(out + g1) =
                make_float2(acc[mi][ni][2] + w1.x, acc[mi][ni][3] + w1.y);
        }
#undef OUT_LOAD
#undef OUT_COMP
}

// ---------------------------------------------------------------------------
// Launch
// ---------------------------------------------------------------------------
extern "C" void kernel_launch(void* const* d_in, const int* in_sizes, int n_in,
                              void* d_out, int out_size)
{
    const float* wp = (const float*)d_in[0];  // [16, 2048, 2048]
    const float* lg = (const float*)d_in[1];  // [16, 128, 1024]
    const float* Wi = (const float*)d_in[2];  // [1024, 2048]
    const float* bi = (const float*)d_in[3];  // [2048]
    const float* Wo = (const float*)d_in[4];  // [1024, 2048]
    const float* bo = (const float*)d_in[5];  // [2048]
    float* out = (float*)d_out;               // [16, 2048, 2048]

    cudaFuncSetAttribute(k_gen,
        cudaFuncAttributeMaxDynamicSharedMemorySize, 2 * P1_STAGE);
    cudaFuncSetAttribute(k_outer,
        cudaFuncAttributeMaxDynamicSharedMemorySize, 2 * P2_STAGE);

    k_split<<<(NROW * NK / 4 + 255) / 256, 256>>>(lg);
    k_wtrans<<<dim3(NC / 32, NK / 32), dim3(32, 8)>>>(Wi, 0);
    k_wtrans<<<dim3(NC / 32, NK / 32), dim3(32, 8)>>>(Wo, 1);

    k_gen<<<dim3(8, 16, 2), 256, 2 * P1_STAGE>>>(bi, bo);
    k_outer<<<dim3(8, 16, 16), 256, 2 * P2_STAGE>>>(wp, out);
}